// round 13
// baseline (speedup 1.0000x reference)
#include <cuda_runtime.h>
#include <cuda_bf16.h>
#include <cuda_fp16.h>
#include <math.h>
#include <stdint.h>

#define B_N   4096
#define INDIM 100
#define NCLS  4
#define OC    16
#define INITD 64
#define PC    32
#define TT    16
#define LVS   32
#define DD    164
#define DP    176
#define MM    33
#define JJ    8448      /* MM*OC*TT */
#define EPS_  1e-5f
#define PREDSZ (B_N*NCLS)

// ---------------- device scratch ----------------
__device__ __align__(16) __nv_bfloat16 g_fh[B_N*DP];
__device__ __align__(16) __nv_bfloat16 g_fl[B_N*DP];
__device__ __align__(16) __nv_bfloat16 g_Bhi[(size_t)JJ*DP];
__device__ __align__(16) __nv_bfloat16 g_Blo[(size_t)JJ*DP];
__device__ float2 g_stats[B_N*MM];            // {mu, rstd}
__device__ __align__(16) float  g_Aj[JJ];
__device__ __align__(16) float  g_Cj[JJ];
__device__ __align__(16) __half g_priorsh[(size_t)B_N*JJ];   // 69 MB fp16
__device__ __align__(16) uint32_t g_lhsplit[512];   // fp16 lh frags [hi|lo]
__device__ float  g_fc1m[3*32*64];
__device__ float  g_fc2m[3*64*80];
__device__ float  g_hsel[B_N*64];
__device__ float  g_hp1[B_N*96];
__device__ float  g_hp2[B_N*192];
__device__ float2 g_gbn1[16*96];
__device__ float2 g_gbn2[16*192];

__device__ __forceinline__ float wsum(float v){
#pragma unroll
    for (int o=16;o>0;o>>=1) v += __shfl_xor_sync(0xffffffffu, v, o);
    return v;
}
__device__ __forceinline__ float wmax(float v){
#pragma unroll
    for (int o=16;o>0;o>>=1) v = fmaxf(v, __shfl_xor_sync(0xffffffffu, v, o));
    return v;
}
__device__ __forceinline__ float sigt(float x){
    float t;
    asm("tanh.approx.f32 %0, %1;" : "=f"(t) : "f"(x*0.5f));
    return fmaf(t, 0.5f, 0.5f);
}

__device__ __forceinline__ void mma16816(float* c, uint32_t a0,uint32_t a1,uint32_t a2,uint32_t a3,
                                         uint32_t b0, uint32_t b1){
    asm volatile("mma.sync.aligned.m16n8k16.row.col.f32.bf16.bf16.f32 "
        "{%0,%1,%2,%3}, {%4,%5,%6,%7}, {%8,%9}, {%0,%1,%2,%3};\n"
        : "+f"(c[0]), "+f"(c[1]), "+f"(c[2]), "+f"(c[3])
        : "r"(a0),"r"(a1),"r"(a2),"r"(a3), "r"(b0),"r"(b1));
}
__device__ __forceinline__ void mmaf16(float* c, uint32_t a0,uint32_t a1,uint32_t a2,uint32_t a3,
                                       uint32_t b0, uint32_t b1){
    asm volatile("mma.sync.aligned.m16n8k16.row.col.f32.f16.f16.f32 "
        "{%0,%1,%2,%3}, {%4,%5,%6,%7}, {%8,%9}, {%0,%1,%2,%3};\n"
        : "+f"(c[0]), "+f"(c[1]), "+f"(c[2]), "+f"(c[3])
        : "r"(a0),"r"(a1),"r"(a2),"r"(a3), "r"(b0),"r"(b1));
}
__device__ __forceinline__ void cpa16(uint32_t dst, const void* src){
    asm volatile("cp.async.cg.shared.global [%0], [%1], 16;\n" :: "r"(dst), "l"(src));
}
__device__ __forceinline__ void ldsm4(uint32_t* r, uint32_t a){
    asm volatile("ldmatrix.sync.aligned.m8n8.x4.shared.b16 {%0,%1,%2,%3}, [%4];"
        : "=r"(r[0]),"=r"(r[1]),"=r"(r[2]),"=r"(r[3]) : "r"(a));
}
__device__ __forceinline__ uint32_t packh2(float a, float b){
    __half2 h = __floats2half2_rn(a, b);
    return *(uint32_t*)&h;
}

// ---------------- entmax over route_w (coalesced) + fold into Bhi/Blo/A/C ----------------
__global__ __launch_bounds__(256) void k_route(const float* __restrict__ rw,
                                               const float* __restrict__ prim,
                                               const float* __restrict__ lng,
                                               const float* __restrict__ lnb){
    __shared__ float st[16*165];
    __shared__ float sP[DD], sG[DD], sB[DD];
    int blk = blockIdx.x;           // 0..527
    int m = blk >> 4, n = blk & 15;
    int tid = threadIdx.x;
    const float* base = rw + (size_t)blk*DD*TT;
    for (int i=tid; i<DD*TT; i+=256){
        int d = i >> 4, t = i & 15;
        st[t*165 + d] = base[i];
    }
    for (int d=tid; d<DD; d+=256){
        sG[d] = lng[d]; sB[d] = lnb[d];
        sP[d] = (m < 32) ? prim[d*PC + m] : 1.f;
    }
    __syncthreads();
    int warp = tid >> 5, lane = tid & 31;
    for (int tt = warp; tt < 16; tt += 8){
        float v[6];
#pragma unroll
        for (int k=0;k<6;k++){
            int d = lane + 32*k;
            v[k] = (d < DD) ? st[tt*165 + d] : -1e30f;
        }
        float mx = -1e30f;
#pragma unroll
        for (int k=0;k<6;k++) mx = fmaxf(mx, v[k]);
        mx = wmax(mx);
        float xt[6];
#pragma unroll
        for (int k=0;k<6;k++) xt[k] = (v[k] - mx)*0.5f;
        float lo = -1.f, hi = 0.f;
        for (int it=0; it<30; it++){
            float mid = 0.5f*(lo+hi);
            float s = 0.f;
#pragma unroll
            for (int k=0;k<6;k++){
                float r = xt[k] - mid;
                if (r > 0.f) s += r*r;
            }
            s = wsum(s);
            if (s > 1.f) lo = mid; else hi = mid;
        }
        float tau = 0.5f*(lo+hi);
        int j = m*256 + n*16 + tt;
        float asum = 0.f, csum = 0.f;
#pragma unroll
        for (int k=0;k<6;k++){
            int d = lane + 32*k;
            if (d < DD){
                float r = xt[k] - tau;
                float p = (r > 0.f) ? r*r : 0.f;
                float gg = sG[d];
                float w  = p*sP[d]*gg;
                __nv_bfloat16 h = __float2bfloat16(w);
                g_Bhi[(size_t)j*DP + d] = h;
                g_Blo[(size_t)j*DP + d] = __float2bfloat16(w - __bfloat162float(h));
                asum += p*gg;
                csum += p*sB[d];
            }
        }
        if (lane < 12){
            __nv_bfloat16 z = __float2bfloat16(0.f);
            g_Bhi[(size_t)j*DP + DD + lane] = z;
            g_Blo[(size_t)j*DP + DD + lane] = z;
        }
        asum = wsum(asum); csum = wsum(csum);
        if (lane == 0){ g_Aj[j] = asum; g_Cj[j] = csum; }
    }
}

// ---------------- small constants ----------------
__device__ float entmax_tau_serial(const float* x, int n){
    float mx = -1e30f;
    for (int i=0;i<n;i++) mx = fmaxf(mx, x[i]);
    float lo = -1.f, hi = 0.f;
    for (int it=0; it<30; it++){
        float mid = 0.5f*(lo+hi);
        float s = 0.f;
        for (int i=0;i<n;i++){
            float r = (x[i]-mx)*0.5f - mid;
            if (r > 0.f) s += r*r;
        }
        if (s > 1.f) lo = mid; else hi = mid;
    }
    return 0.5f*(lo+hi);
}

__global__ __launch_bounds__(256) void k_const2(const float* __restrict__ leaves,
                                                const float* __restrict__ m1w,
                                                const float* __restrict__ fc1w,
                                                const float* __restrict__ m2w,
                                                const float* __restrict__ fc2w){
    __shared__ float mask1[3*64];
    __shared__ float mask2[3*80];
    __shared__ float slh[LVS*TT];
    int tid = threadIdx.x;
    if (tid < 32){
        float s = 0.f;
        for (int t=0;t<TT;t++){ float v = leaves[tid*TT+t]; s += v*v; }
        float inv = 1.f / fmaxf(sqrtf(s), 1e-12f);
        for (int t=0;t<TT;t++) slh[tid*TT+t] = leaves[tid*TT+t]*inv;
    }
    if (tid < 3){
        const float* row = m1w + tid*64;
        float tau = entmax_tau_serial(row, 64);
        float mx = -1e30f;
        for (int i=0;i<64;i++) mx = fmaxf(mx, row[i]);
        for (int i=0;i<64;i++){
            float r = (row[i]-mx)*0.5f - tau;
            mask1[tid*64+i] = (r > 0.f) ? r*r : 0.f;
        }
    }
    if (tid >= 3 && tid < 6){
        int p = tid-3;
        const float* row = m2w + p*80;
        float tau = entmax_tau_serial(row, 80);
        float mx = -1e30f;
        for (int i=0;i<80;i++) mx = fmaxf(mx, row[i]);
        for (int i=0;i<80;i++){
            float r = (row[i]-mx)*0.5f - tau;
            mask2[p*80+i] = (r > 0.f) ? r*r : 0.f;
        }
    }
    __syncthreads();
    if (tid < 32){
        int ln = tid, g = ln >> 2, t = ln & 3;
#pragma unroll
        for (int nt=0;nt<4;nt++){
            const float* lr = slh + (nt*8 + g)*TT;
            float e0 = lr[2*t], e1 = lr[2*t+1], e2 = lr[2*t+8], e3 = lr[2*t+9];
            float h0 = __half2float(__float2half(e0));
            float h1 = __half2float(__float2half(e1));
            float h2 = __half2float(__float2half(e2));
            float h3 = __half2float(__float2half(e3));
            g_lhsplit[ln*8 + nt*2 + 0] = packh2(h0, h1);
            g_lhsplit[ln*8 + nt*2 + 1] = packh2(h2, h3);
            g_lhsplit[256 + ln*8 + nt*2 + 0] = packh2(e0-h0, e1-h1);
            g_lhsplit[256 + ln*8 + nt*2 + 1] = packh2(e2-h2, e3-h3);
        }
    }
    for (int i=tid; i<3*32*64; i+=256){
        int p = i/2048, d = i & 63;
        g_fc1m[i] = fc1w[i]*mask1[p*64+d];
    }
    for (int i=tid; i<3*64*80; i+=256){
        int p = i/5120, d = i % 80;
        g_fc2m[i] = fc2w[i]*mask2[p*80+d];
    }
}

// ---------------- f batched: 16 rows/block, prim amortized ----------------
#define FB 16
__global__ __launch_bounds__(256) void k_f(const float* __restrict__ x,
                                           const float* __restrict__ iw,
                                           const float* __restrict__ ib,
                                           const float* __restrict__ prim){
    __shared__ float sprim[DD*33];      // 21.6 KB
    __shared__ float sf[FB*165];        // 10.5 KB
    int b0 = blockIdx.x*FB, tid = threadIdx.x;
    for (int i = tid; i < DD*PC; i += 256){
        int d = i >> 5, mm = i & 31;
        sprim[d*33 + mm] = prim[i];
    }
    for (int i = tid; i < FB*INDIM; i += 256){
        int bl = i/INDIM, d = i - bl*INDIM;
        sf[bl*165 + d] = x[(size_t)(b0+bl)*INDIM + d];
    }
    __syncthreads();
    // init: 64 outputs x 16 rows; o = tid&63, 4 row-groups
    {
        int o = tid & 63, bq = tid >> 6;
        const float* wr = iw + o*INDIM;
        float bias = ib[o];
        for (int bl = bq; bl < FB; bl += 4){
            const float* xr = sf + bl*165;
            float a = bias;
            for (int d = 0; d < INDIM; d++) a += xr[d]*wr[d];
            sf[bl*165 + INDIM + o] = a;
        }
    }
    __syncthreads();
    // bf16 splits
    for (int i = tid; i < FB*DP; i += 256){
        int bl = i/DP, dp = i - bl*DP;
        float v = (dp < DD) ? sf[bl*165 + dp] : 0.f;
        __nv_bfloat16 h = __float2bfloat16(v);
        g_fh[(size_t)(b0+bl)*DP + dp] = h;
        g_fl[(size_t)(b0+bl)*DP + dp] = __float2bfloat16(v - __bfloat162float(h));
    }
    // stats: 528 (bl,m) pairs
    for (int p = tid; p < FB*MM; p += 256){
        int bl = p/MM, m = p - bl*MM;
        const float* fr = sf + bl*165;
        float s = 0.f, s2 = 0.f;
        if (m < 32){
            for (int d = 0; d < DD; d++){
                float c = fr[d]*sprim[d*33 + m];
                s += c; s2 += c*c;
            }
        } else {
            for (int d = 0; d < DD; d++){ float c = fr[d]; s += c; s2 += c*c; }
        }
        float mu = s*(1.f/DD);
        float var = s2*(1.f/DD) - mu*mu;
        g_stats[(b0+bl)*MM + m] = make_float2(mu, rsqrtf(fmaxf(var,0.f)+EPS_));
    }
}

// ---------------- tensor-core GEMM: 3-stage cp.async(.cg), ldmatrix, fp16 out ----------------
__global__ __launch_bounds__(256, 2) void k_gemm(){
    extern __shared__ uint32_t sm[];
    const int tid = threadIdx.x;
    const int j0 = blockIdx.x*128, b0 = blockIdx.y*128;
    const uint32_t smb = (uint32_t)__cvta_generic_to_shared(sm);
    const int warp = tid >> 5, lane = tid & 31;
    const int t = lane & 3;
    const int moff = (warp >> 2)*64, joff = (warp & 3)*32;

    const uint32_t aoffA = (uint32_t)((moff + (lane & 15))*12*4) + ((lane >> 4)*16);
    const uint32_t aoffB = (uint32_t)((joff + (lane & 7) + ((lane >> 4)*8))*12*4)
                         + (((lane >> 3) & 1)*16);

    float acc[4][4][4];
#pragma unroll
    for (int mt=0;mt<4;mt++)
#pragma unroll
        for (int nt=0;nt<4;nt++)
#pragma unroll
            for (int q=0;q<4;q++) acc[mt][nt][q] = 0.f;

    auto issue = [&](int kt, int s){
#pragma unroll
        for (int i0=0;i0<4;i0++){
            int i = tid + i0*256;
            int half = i >> 9, ii = i & 511, split = ii >> 8, r = (ii & 255) >> 1, c = ii & 1;
            const __nv_bfloat16* src;
            if (half == 0) src = (split ? g_fl  : g_fh ) + (size_t)(b0+r)*DP + kt*16 + c*8;
            else           src = (split ? g_Blo : g_Bhi) + (size_t)(j0+r)*DP + kt*16 + c*8;
            uint32_t dst = smb + (uint32_t)((s*6144 + half*3072 + split*1536 + r*12 + c*4)*4);
            cpa16(dst, src);
        }
        asm volatile("cp.async.commit_group;\n"::);
    };

    issue(0, 0);
    issue(1, 1);

#pragma unroll 1
    for (int kt = 0; kt < 11; kt++){
        int s = kt % 3;
        if (kt < 10) asm volatile("cp.async.wait_group 1;\n"::);
        else         asm volatile("cp.async.wait_group 0;\n"::);
        __syncthreads();

        const uint32_t baseA = smb + (uint32_t)(s*6144*4);
        const uint32_t baseB = baseA + 3072*4;

        uint32_t bh[4][2], bl[4][2];
#pragma unroll
        for (int p=0;p<2;p++){
            uint32_t r[4];
            ldsm4(r, baseB + aoffB + (uint32_t)(p*16*12*4));
            bh[2*p][0]=r[0]; bh[2*p][1]=r[1]; bh[2*p+1][0]=r[2]; bh[2*p+1][1]=r[3];
            ldsm4(r, baseB + 1536*4 + aoffB + (uint32_t)(p*16*12*4));
            bl[2*p][0]=r[0]; bl[2*p][1]=r[1]; bl[2*p+1][0]=r[2]; bl[2*p+1][1]=r[3];
        }
#pragma unroll
        for (int mt=0;mt<4;mt++){
            uint32_t ah[4], al[4];
            ldsm4(ah, baseA + aoffA + (uint32_t)(mt*16*12*4));
            ldsm4(al, baseA + 1536*4 + aoffA + (uint32_t)(mt*16*12*4));
#pragma unroll
            for (int nt=0;nt<4;nt++){
                mma16816(acc[mt][nt], ah[0],ah[1],ah[2],ah[3], bh[nt][0], bh[nt][1]);
                mma16816(acc[mt][nt], ah[0],ah[1],ah[2],ah[3], bl[nt][0], bl[nt][1]);
                mma16816(acc[mt][nt], al[0],al[1],al[2],al[3], bh[nt][0], bh[nt][1]);
            }
        }
        if (kt + 2 < 11) issue(kt+2, (kt+2) % 3);
    }

    const int g = lane >> 2;
    const int mcls = blockIdx.x >> 1;
    float2 ajv[4], cjv[4];
#pragma unroll
    for (int nt=0;nt<4;nt++){
        int j = j0 + joff + nt*8 + 2*t;
        ajv[nt] = *(const float2*)&g_Aj[j];
        cjv[nt] = *(const float2*)&g_Cj[j];
    }
#pragma unroll
    for (int mt=0;mt<4;mt++){
#pragma unroll
        for (int io=0; io<2; io++){
            int b = b0 + moff + mt*16 + g + io*8;
            float2 st = g_stats[b*MM + mcls];
            float rs = st.y, rm = st.y*st.x;
#pragma unroll
            for (int nt=0;nt<4;nt++){
                float c0 = acc[mt][nt][io*2], c1 = acc[mt][nt][io*2+1];
                float o0 = rs*c0 - rm*ajv[nt].x + cjv[nt].x;
                float o1 = rs*c1 - rm*ajv[nt].y + cjv[nt].y;
                __half2 h2 = __floats2half2_rn(o0, o1);
                *(__half2*)&g_priorsh[(size_t)b*JJ + j0 + joff + nt*8 + 2*t] = h2;
            }
        }
    }
}

// ---------------- per-b routing reduce (fp16 priors + f16 MMA votes, tanh sigmoid) ----------------
#define RSM_BYTES (528*24*2 + 528*34*2)
__global__ __launch_bounds__(256, 3) void k_reduce(const float* __restrict__ y,
                                                const float* __restrict__ thr,
                                                const float* __restrict__ clg,
                                                const float* __restrict__ clb,
                                                float* __restrict__ out){
    extern __shared__ __half hsm[];
    __half* sph = hsm;                 // [528][24] fp16 priors
    __half* svh = hsm + 528*24;        // [528][34] votes fp16
    __shared__ __half2 vb2[16*17];
    __shared__ float wg[528];
    __shared__ float sh[256];
    __shared__ float sy[4];
    __shared__ float snorm[16];
    __shared__ float sclg[16], sclb[16];
    __shared__ float smx[16], sinv[16];

    int b = blockIdx.x, tid = threadIdx.x;
    int warp = tid >> 5, lane = tid & 31;
    int g = lane >> 2, t = lane & 3;
    {
        const uint4* prow = (const uint4*)(g_priorsh + (size_t)b*JJ);
        for (int i=tid; i<1056; i+=256){
            uint4 v = prow[i];
            int mn = i >> 1, hf = i & 1;
            *(uint4*)&sph[mn*24 + hf*8] = v;
        }
    }
    if (tid < 4) sy[tid] = y[(size_t)b*4 + tid];
    if (tid < 16){ sclg[tid] = clg[tid]; sclb[tid] = clb[tid]; }

    uint32_t lbh[4][2], lbl[4][2];
    {
        const uint4* lf = (const uint4*)(g_lhsplit + lane*8);
        uint4 a0 = lf[0], a1 = lf[1];
        lbh[0][0]=a0.x; lbh[0][1]=a0.y; lbh[1][0]=a0.z; lbh[1][1]=a0.w;
        lbh[2][0]=a1.x; lbh[2][1]=a1.y; lbh[3][0]=a1.z; lbh[3][1]=a1.w;
        const uint4* lg = (const uint4*)(g_lhsplit + 256 + lane*8);
        uint4 b0v = lg[0], b1v = lg[1];
        lbl[0][0]=b0v.x; lbl[0][1]=b0v.y; lbl[1][0]=b0v.z; lbl[1][1]=b0v.w;
        lbl[2][0]=b1v.x; lbl[2][1]=b1v.y; lbl[3][0]=b1v.z; lbl[3][1]=b1v.w;
    }
    __syncthreads();

    const uint32_t spb = (uint32_t)__cvta_generic_to_shared(sph);
    for (int mt = warp; mt < 33; mt += 8){
        uint32_t ap[4];
        ldsm4(ap, spb + (uint32_t)(((mt*16 + (lane & 15))*24 + (lane >> 4)*8)*2));
        int r0 = mt*16 + g, r1 = r0 + 8;
#pragma unroll
        for (int nt=0;nt<4;nt++){
            float c[4] = {0.f,0.f,0.f,0.f};
            mmaf16(c, ap[0],ap[1],ap[2],ap[3], lbh[nt][0], lbh[nt][1]);
            mmaf16(c, ap[0],ap[1],ap[2],ap[3], lbl[nt][0], lbl[nt][1]);
            *(__half2*)&svh[r0*34 + nt*8 + 2*t] = __floats2half2_rn(sigt(c[0]), sigt(c[1]));
            *(__half2*)&svh[r1*34 + nt*8 + 2*t] = __floats2half2_rn(sigt(c[2]), sigt(c[3]));
        }
    }
    __syncthreads();
    {
        const __half2* sv2 = (const __half2*)svh;
        for (int i=tid; i<256; i+=256){
            int n = i >> 4, lp = i & 15;
            float ax = 0.f, ay = 0.f;
            for (int m=0;m<MM;m++){
                float2 f = __half22float2(sv2[(m*16+n)*17 + lp]);
                ax += f.x; ay += f.y;
            }
            vb2[n*17 + lp] = __floats2half2_rn(ax*(1.f/33.f), ay*(1.f/33.f));
        }
    }
    __syncthreads();
    {
        const __half2* sv2 = (const __half2*)svh;
        for (int i=tid; i<528; i+=256){
            int n = i & 15;
            float a = 0.f;
            for (int lp=0; lp<16; lp++){
                float2 v = __half22float2(sv2[i*17 + lp]);
                float2 m = __half22float2(vb2[n*17 + lp]);
                float dx = v.x - m.x, dy = v.y - m.y;
                a += dx*dx + dy*dy;
            }
            float tv = thr[i];
            float w = tv*tv - a*(1.f/32.f);
            wg[i] = (w > 0.f) ? w : 0.f;
        }
    }
    __syncthreads();
    if (tid < 16){
        float mx = -1e30f;
        for (int m=0;m<MM;m++) mx = fmaxf(mx, wg[m*16+tid]);
        smx[tid] = mx;
    }
    __syncthreads();
    for (int i=tid; i<528; i+=256) wg[i] = __expf(wg[i] - smx[i & 15]);
    __syncthreads();
    if (tid < 16){
        float s = 0.f;
        for (int m=0;m<MM;m++) s += wg[m*16+tid];
        sinv[tid] = 1.f/s;
    }
    __syncthreads();
    if (tid < 256){
        int n = tid >> 4, tt = tid & 15;
        float a = 0.f;
        for (int m=0;m<MM;m++) a += wg[m*16+n]*__half2float(sph[(m*16+n)*24 + tt]);
        sh[tid] = a * sinv[n];
    }
    __syncthreads();
    if (tid < 16){
        int n = tid;
        float s = 0.f, s2 = 0.f;
        for (int tt=0;tt<16;tt++){ float v = sh[n*16+tt]; s += v; s2 += v*v; }
        float mu = s*(1.f/16.f);
        float var = s2*(1.f/16.f) - mu*mu;
        float r = rsqrtf(fmaxf(var,0.f) + EPS_);
        float nn = 0.f;
        for (int tt=0;tt<16;tt++){
            float h = (sh[n*16+tt]-mu)*r*sclg[tt] + sclb[tt];
            sh[n*16+tt] = h;
            nn += h*h;
        }
        snorm[n] = sqrtf(nn);
    }
    __syncthreads();
    if (tid < 4)
        out[(size_t)b*4 + tid] = snorm[tid*4]+snorm[tid*4+1]+snorm[tid*4+2]+snorm[tid*4+3];
    if (tid < 64){
        int s = tid >> 4, tt = tid & 15;
        float a = 0.f;
#pragma unroll
        for (int c=0;c<4;c++) a += sy[c]*sh[(s*4+c)*16 + tt];
        g_hsel[(size_t)b*64 + tid] = a;
    }
}

// ---------------- decoder ----------------
__global__ __launch_bounds__(256) void k_dec1(){
    __shared__ float w[3*32*64];
    __shared__ float hs[32*65];
    int b0 = blockIdx.x*32, tid = threadIdx.x;
    for (int i=tid; i<6144; i+=256) w[i] = g_fc1m[i];
    for (int i=tid; i<2048; i+=256){
        int bl = i >> 6, d = i & 63;
        hs[bl*65 + d] = g_hsel[(size_t)(b0+bl)*64 + d];
    }
    __syncthreads();
    for (int idx=tid; idx<3072; idx+=256){
        int po = idx >> 5, bl = idx & 31;
        const float* wr = w + po*64;
        const float* hr = hs + bl*65;
        float a = 0.f;
#pragma unroll
        for (int d=0; d<64; d++) a += hr[d]*wr[d];
        g_hp1[(size_t)(b0+bl)*96 + po] = a;
    }
}

__global__ __launch_bounds__(256) void k_gbn1(const float* __restrict__ bg, const float* __restrict__ bb){
    int w = (blockIdx.x*256 + threadIdx.x) >> 5;
    int lane = threadIdx.x & 31;
    if (w >= 16*96) return;
    int g = w/96, k = w - g*96;
    const float* p = g_hp1 + (size_t)g*256*96 + k;
    float s = 0.f, s2 = 0.f;
#pragma unroll
    for (int i=0;i<8;i++){ float v = p[(size_t)(lane + i*32)*96]; s += v; s2 += v*v; }
    s = wsum(s); s2 = wsum(s2);
    if (lane == 0){
        float mu = s*(1.f/256.f);
        float var = s2*(1.f/256.f) - mu*mu;
        float r = rsqrtf(fmaxf(var,0.f) + EPS_);
        float a = bg[k]*r;
        g_gbn1[g*96 + k] = make_float2(a, bb[k] - mu*a);
    }
}

__global__ __launch_bounds__(256) void k_gbn2(const float* __restrict__ bg, const float* __restrict__ bb){
    int w = (blockIdx.x*256 + threadIdx.x) >> 5;
    int lane = threadIdx.x & 31;
    if (w >= 16*192) return;
    int g = w/192, k = w - g*192;
    const float* p = g_hp2 + (size_t)g*256*192 + k;
    float s = 0.f, s2 = 0.f;
#pragma unroll
    for (int i=0;i<8;i++){ float v = p[(size_t)(lane + i*32)*192]; s += v; s2 += v*v; }
    s = wsum(s); s2 = wsum(s2);
    if (lane == 0){
        float mu = s*(1.f/256.f);
        float var = s2*(1.f/256.f) - mu*mu;
        float r = rsqrtf(fmaxf(var,0.f) + EPS_);
        float a = bg[k]*r;
        g_gbn2[g*192 + k] = make_float2(a, bb[k] - mu*a);
    }
}

__global__ __launch_bounds__(256) void k_dec2(){
    extern __shared__ float dsm2[];
    float* w  = dsm2;           // 15360
    float* hs = dsm2 + 15360;   // 32*81
    int b0 = blockIdx.x*32, tid = threadIdx.x;
    for (int i=tid; i<15360; i+=256) w[i] = g_fc2m[i];
    for (int i=tid; i<2560; i+=256){
        int bl = i/80, d = i - bl*80;
        int b = b0 + bl;
        float v;
        if (d < 64){
            v = g_hsel[(size_t)b*64 + d];
        } else {
            int oo = d - 64, gg = b >> 8;
            v = 0.f;
#pragma unroll
            for (int p=0;p<3;p++){
                int k1 = p*32 + oo, k2 = k1 + 16;
                float2 t1 = g_gbn1[gg*96 + k1], t2 = g_gbn1[gg*96 + k2];
                float x1 = g_hp1[(size_t)b*96 + k1]*t1.x + t1.y;
                float x2 = g_hp1[(size_t)b*96 + k2]*t2.x + t2.y;
                float sg = 1.f/(1.f + __expf(-x1));
                v += fmaxf(sg*x2, 0.f);
            }
        }
        hs[bl*81 + d] = v;
    }
    __syncthreads();
    for (int idx=tid; idx<6144; idx+=256){
        int po = idx >> 5, bl = idx & 31;
        const float* wr = w + po*80;
        const float* hr = hs + bl*81;
        float a = 0.f;
#pragma unroll
        for (int d=0; d<80; d++) a += hr[d]*wr[d];
        g_hp2[(size_t)(b0+bl)*192 + po] = a;
    }
}

__global__ __launch_bounds__(256) void k_glu2rec(const float* __restrict__ dw,
                                                 const float* __restrict__ db,
                                                 float* __restrict__ out){
    __shared__ float so2[8*33];
    int b0 = blockIdx.x*8, tid = threadIdx.x;
    {
        int bl = tid >> 5, o = tid & 31;
        int b = b0 + bl, g = b >> 8;
        float a = 0.f;
#pragma unroll
        for (int p=0;p<3;p++){
            int k1 = p*64 + o, k2 = k1 + 32;
            float2 t1 = g_gbn2[g*192 + k1], t2 = g_gbn2[g*192 + k2];
            float x1 = g_hp2[(size_t)b*192 + k1]*t1.x + t1.y;
            float x2 = g_hp2[(size_t)b*192 + k2]*t2.x + t2.y;
            float sg = 1.f/(1.f + __expf(-x1));
            a += fmaxf(sg*x2, 0.f);
        }
        so2[bl*33 + o] = a;
    }
    __syncthreads();
    for (int i=tid; i<800; i+=256){
        int bl = i/100, o = i - bl*100;
        float a = db[o];
        const float* wr = dw + o*32;
        const float* sr = so2 + bl*33;
#pragma unroll
        for (int k=0;k<32;k++) a += sr[k]*wr[k];
        out[PREDSZ + (size_t)(b0+bl)*100 + o] = a;
    }
}

// ---------------- launcher ----------------
extern "C" void kernel_launch(void* const* d_in, const int* in_sizes, int n_in,
                              void* d_out, int out_size){
    const float* x      = (const float*)d_in[0];
    const float* y      = (const float*)d_in[1];
    const float* init_w = (const float*)d_in[2];
    const float* init_b = (const float*)d_in[3];
    const float* lng    = (const float*)d_in[4];
    const float* lnb    = (const float*)d_in[5];
    const float* prim   = (const float*)d_in[6];
    const float* routew = (const float*)d_in[7];
    const float* thr    = (const float*)d_in[8];
    const float* leaves = (const float*)d_in[9];
    const float* clg    = (const float*)d_in[10];
    const float* clb    = (const float*)d_in[11];
    const float* m1w    = (const float*)d_in[12];
    const float* fc1w   = (const float*)d_in[13];
    const float* bn1g   = (const float*)d_in[15];
    const float* bn1b   = (const float*)d_in[16];
    const float* m2w    = (const float*)d_in[17];
    const float* fc2w   = (const float*)d_in[18];
    const float* bn2g   = (const float*)d_in[20];
    const float* bn2b   = (const float*)d_in[21];
    const float* decw   = (const float*)d_in[22];
    const float* decb   = (const float*)d_in[23];
    float* out = (float*)d_out;

    cudaFuncSetAttribute(k_gemm,   cudaFuncAttributeMaxDynamicSharedMemorySize, 18432*4);
    cudaFuncSetAttribute(k_reduce, cudaFuncAttributeMaxDynamicSharedMemorySize, RSM_BYTES);
    cudaFuncSetAttribute(k_dec2,   cudaFuncAttributeMaxDynamicSharedMemorySize, (15360+32*81)*4);

    k_route<<<528, 256>>>(routew, prim, lng, lnb);
    k_const2<<<1, 256>>>(leaves, m1w, fc1w, m2w, fc2w);
    k_f<<<B_N/FB, 256>>>(x, init_w, init_b, prim);
    {
        dim3 grid(JJ/128, B_N/128);
        k_gemm<<<grid, 256, 18432*4>>>();
    }
    k_reduce<<<B_N, 256, RSM_BYTES>>>(y, thr, clg, clb, out);
    k_dec1<<<B_N/32, 256>>>();
    k_gbn1<<<192, 256>>>(bn1g, bn1b);
    k_dec2<<<B_N/32, 256, (15360+32*81)*4>>>();
    k_gbn2<<<384, 256>>>(bn2g, bn2b);
    k_glu2rec<<<B_N/8, 256>>>(decw, decb, out);
}

// round 14
// speedup vs baseline: 1.1655x; 1.1655x over previous
#include <cuda_runtime.h>
#include <cuda_bf16.h>
#include <cuda_fp16.h>
#include <math.h>
#include <stdint.h>

#define B_N   4096
#define INDIM 100
#define NCLS  4
#define OC    16
#define INITD 64
#define PC    32
#define TT    16
#define LVS   32
#define DD    164
#define DP    176
#define MM    33
#define JJ    8448      /* MM*OC*TT */
#define EPS_  1e-5f
#define PREDSZ (B_N*NCLS)

// ---------------- device scratch ----------------
__device__ __align__(16) __half g_fh[B_N*DP];                // fp16 f
__device__ __align__(16) __half g_Bh[(size_t)JJ*DP];         // fp16 W2 (j-major)
__device__ float2 g_stats[B_N*MM];            // {mu, rstd}
__device__ __align__(16) float  g_Aj[JJ];
__device__ __align__(16) float  g_Cj[JJ];
__device__ __align__(16) __half g_priorsh[(size_t)B_N*JJ];   // 69 MB fp16
__device__ __align__(16) uint32_t g_lhsplit[512];   // fp16 lh frags [hi|lo]
__device__ float  g_fc1m[3*32*64];
__device__ float  g_fc2m[3*64*80];
__device__ float  g_hsel[B_N*64];
__device__ float  g_hp1[B_N*96];
__device__ float  g_hp2[B_N*192];
__device__ float2 g_gbn1[16*96];
__device__ float2 g_gbn2[16*192];

__device__ __forceinline__ float wsum(float v){
#pragma unroll
    for (int o=16;o>0;o>>=1) v += __shfl_xor_sync(0xffffffffu, v, o);
    return v;
}
__device__ __forceinline__ float wmax(float v){
#pragma unroll
    for (int o=16;o>0;o>>=1) v = fmaxf(v, __shfl_xor_sync(0xffffffffu, v, o));
    return v;
}
__device__ __forceinline__ float sigt(float x){
    float t;
    asm("tanh.approx.f32 %0, %1;" : "=f"(t) : "f"(x*0.5f));
    return fmaf(t, 0.5f, 0.5f);
}

__device__ __forceinline__ void mmaf16(float* c, uint32_t a0,uint32_t a1,uint32_t a2,uint32_t a3,
                                       uint32_t b0, uint32_t b1){
    asm volatile("mma.sync.aligned.m16n8k16.row.col.f32.f16.f16.f32 "
        "{%0,%1,%2,%3}, {%4,%5,%6,%7}, {%8,%9}, {%0,%1,%2,%3};\n"
        : "+f"(c[0]), "+f"(c[1]), "+f"(c[2]), "+f"(c[3])
        : "r"(a0),"r"(a1),"r"(a2),"r"(a3), "r"(b0),"r"(b1));
}
__device__ __forceinline__ void cpa16(uint32_t dst, const void* src){
    asm volatile("cp.async.ca.shared.global [%0], [%1], 16;\n" :: "r"(dst), "l"(src));
}
__device__ __forceinline__ void ldsm4(uint32_t* r, uint32_t a){
    asm volatile("ldmatrix.sync.aligned.m8n8.x4.shared.b16 {%0,%1,%2,%3}, [%4];"
        : "=r"(r[0]),"=r"(r[1]),"=r"(r[2]),"=r"(r[3]) : "r"(a));
}
__device__ __forceinline__ uint32_t packh2(float a, float b){
    __half2 h = __floats2half2_rn(a, b);
    return *(uint32_t*)&h;
}

// ---------------- entmax over route_w (coalesced) + fold into Bh/A/C ----------------
__global__ __launch_bounds__(256) void k_route(const float* __restrict__ rw,
                                               const float* __restrict__ prim,
                                               const float* __restrict__ lng,
                                               const float* __restrict__ lnb){
    __shared__ float st[16*165];
    __shared__ float sP[DD], sG[DD], sB[DD];
    int blk = blockIdx.x;           // 0..527
    int m = blk >> 4, n = blk & 15;
    int tid = threadIdx.x;
    const float* base = rw + (size_t)blk*DD*TT;
    for (int i=tid; i<DD*TT; i+=256){
        int d = i >> 4, t = i & 15;
        st[t*165 + d] = base[i];
    }
    for (int d=tid; d<DD; d+=256){
        sG[d] = lng[d]; sB[d] = lnb[d];
        sP[d] = (m < 32) ? prim[d*PC + m] : 1.f;
    }
    __syncthreads();
    int warp = tid >> 5, lane = tid & 31;
    for (int tt = warp; tt < 16; tt += 8){
        float v[6];
#pragma unroll
        for (int k=0;k<6;k++){
            int d = lane + 32*k;
            v[k] = (d < DD) ? st[tt*165 + d] : -1e30f;
        }
        float mx = -1e30f;
#pragma unroll
        for (int k=0;k<6;k++) mx = fmaxf(mx, v[k]);
        mx = wmax(mx);
        float xt[6];
#pragma unroll
        for (int k=0;k<6;k++) xt[k] = (v[k] - mx)*0.5f;
        float lo = -1.f, hi = 0.f;
        for (int it=0; it<30; it++){
            float mid = 0.5f*(lo+hi);
            float s = 0.f;
#pragma unroll
            for (int k=0;k<6;k++){
                float r = xt[k] - mid;
                if (r > 0.f) s += r*r;
            }
            s = wsum(s);
            if (s > 1.f) lo = mid; else hi = mid;
        }
        float tau = 0.5f*(lo+hi);
        int j = m*256 + n*16 + tt;
        float asum = 0.f, csum = 0.f;
#pragma unroll
        for (int k=0;k<6;k++){
            int d = lane + 32*k;
            if (d < DD){
                float r = xt[k] - tau;
                float p = (r > 0.f) ? r*r : 0.f;
                float gg = sG[d];
                float w  = p*sP[d]*gg;
                g_Bh[(size_t)j*DP + d] = __float2half(w);
                asum += p*gg;
                csum += p*sB[d];
            }
        }
        if (lane < 12){
            g_Bh[(size_t)j*DP + DD + lane] = __float2half(0.f);
        }
        asum = wsum(asum); csum = wsum(csum);
        if (lane == 0){ g_Aj[j] = asum; g_Cj[j] = csum; }
    }
}

// ---------------- small constants ----------------
__device__ float entmax_tau_serial(const float* x, int n){
    float mx = -1e30f;
    for (int i=0;i<n;i++) mx = fmaxf(mx, x[i]);
    float lo = -1.f, hi = 0.f;
    for (int it=0; it<30; it++){
        float mid = 0.5f*(lo+hi);
        float s = 0.f;
        for (int i=0;i<n;i++){
            float r = (x[i]-mx)*0.5f - mid;
            if (r > 0.f) s += r*r;
        }
        if (s > 1.f) lo = mid; else hi = mid;
    }
    return 0.5f*(lo+hi);
}

__global__ __launch_bounds__(256) void k_const2(const float* __restrict__ leaves,
                                                const float* __restrict__ m1w,
                                                const float* __restrict__ fc1w,
                                                const float* __restrict__ m2w,
                                                const float* __restrict__ fc2w){
    __shared__ float mask1[3*64];
    __shared__ float mask2[3*80];
    __shared__ float slh[LVS*TT];
    int tid = threadIdx.x;
    if (tid < 32){
        float s = 0.f;
        for (int t=0;t<TT;t++){ float v = leaves[tid*TT+t]; s += v*v; }
        float inv = 1.f / fmaxf(sqrtf(s), 1e-12f);
        for (int t=0;t<TT;t++) slh[tid*TT+t] = leaves[tid*TT+t]*inv;
    }
    if (tid < 3){
        const float* row = m1w + tid*64;
        float tau = entmax_tau_serial(row, 64);
        float mx = -1e30f;
        for (int i=0;i<64;i++) mx = fmaxf(mx, row[i]);
        for (int i=0;i<64;i++){
            float r = (row[i]-mx)*0.5f - tau;
            mask1[tid*64+i] = (r > 0.f) ? r*r : 0.f;
        }
    }
    if (tid >= 3 && tid < 6){
        int p = tid-3;
        const float* row = m2w + p*80;
        float tau = entmax_tau_serial(row, 80);
        float mx = -1e30f;
        for (int i=0;i<80;i++) mx = fmaxf(mx, row[i]);
        for (int i=0;i<80;i++){
            float r = (row[i]-mx)*0.5f - tau;
            mask2[p*80+i] = (r > 0.f) ? r*r : 0.f;
        }
    }
    __syncthreads();
    if (tid < 32){
        int ln = tid, g = ln >> 2, t = ln & 3;
#pragma unroll
        for (int nt=0;nt<4;nt++){
            const float* lr = slh + (nt*8 + g)*TT;
            float e0 = lr[2*t], e1 = lr[2*t+1], e2 = lr[2*t+8], e3 = lr[2*t+9];
            float h0 = __half2float(__float2half(e0));
            float h1 = __half2float(__float2half(e1));
            float h2 = __half2float(__float2half(e2));
            float h3 = __half2float(__float2half(e3));
            g_lhsplit[ln*8 + nt*2 + 0] = packh2(h0, h1);
            g_lhsplit[ln*8 + nt*2 + 1] = packh2(h2, h3);
            g_lhsplit[256 + ln*8 + nt*2 + 0] = packh2(e0-h0, e1-h1);
            g_lhsplit[256 + ln*8 + nt*2 + 1] = packh2(e2-h2, e3-h3);
        }
    }
    for (int i=tid; i<3*32*64; i+=256){
        int p = i/2048, d = i & 63;
        g_fc1m[i] = fc1w[i]*mask1[p*64+d];
    }
    for (int i=tid; i<3*64*80; i+=256){
        int p = i/5120, d = i % 80;
        g_fc2m[i] = fc2w[i]*mask2[p*80+d];
    }
}

// ---------------- f, fp16, per-(b,m) LN stats ----------------
__global__ __launch_bounds__(256) void k_f(const float* __restrict__ x,
                                           const float* __restrict__ iw,
                                           const float* __restrict__ ib,
                                           const float* __restrict__ prim){
    __shared__ float sx[INDIM];
    __shared__ float sf[DD];
    __shared__ float sprim[DD*33];
    int b = blockIdx.x, tid = threadIdx.x;
    if (tid < INDIM) sx[tid] = x[(size_t)b*INDIM + tid];
    for (int i = tid; i < DD*PC; i += 256){
        int d = i >> 5, mm = i & 31;
        sprim[d*33 + mm] = prim[i];
    }
    __syncthreads();
    {
        int o = tid >> 2, q = tid & 3;
        float a = 0.f;
        for (int d = q; d < INDIM; d += 4) a += sx[d]*iw[o*INDIM + d];
        a += __shfl_xor_sync(0xffffffffu, a, 1);
        a += __shfl_xor_sync(0xffffffffu, a, 2);
        if (q == 0) sf[INDIM + o] = a + ib[o];
    }
    if (tid < INDIM) sf[tid] = sx[tid];
    __syncthreads();
    if (tid < DP){
        float v = (tid < DD) ? sf[tid] : 0.f;
        g_fh[(size_t)b*DP + tid] = __float2half(v);
    }
    int warp = tid >> 5, lane = tid & 31;
    for (int m = warp; m < MM; m += 8){
        float s = 0.f, s2 = 0.f;
        for (int d = lane; d < DD; d += 32){
            float p = (m < 32) ? sprim[d*33 + m] : 1.f;
            float c = sf[d]*p;
            s += c; s2 += c*c;
        }
        s = wsum(s); s2 = wsum(s2);
        if (lane == 0){
            float mu = s*(1.f/DD);
            float var = s2*(1.f/DD) - mu*mu;
            g_stats[b*MM + m] = make_float2(mu, rsqrtf(fmaxf(var,0.f)+EPS_));
        }
    }
}

// ---------------- tensor-core GEMM v5: single-product fp16, 3-stage cp.async ----------------
// smem/stage: A 128x12u32 (1536) + B 128x12u32 (1536); 3 stages = 9216 u32 = 36 KB
__global__ __launch_bounds__(256, 2) void k_gemm(){
    extern __shared__ uint32_t sm[];
    const int tid = threadIdx.x;
    const int j0 = blockIdx.x*128, b0 = blockIdx.y*128;
    const uint32_t smb = (uint32_t)__cvta_generic_to_shared(sm);
    const int warp = tid >> 5, lane = tid & 31;
    const int t = lane & 3;
    const int moff = (warp >> 2)*64, joff = (warp & 3)*32;

    const uint32_t aoffA = (uint32_t)((moff + (lane & 15))*12*4) + ((lane >> 4)*16);
    const uint32_t aoffB = (uint32_t)((joff + (lane & 7) + ((lane >> 4)*8))*12*4)
                         + (((lane >> 3) & 1)*16);

    float acc[4][4][4];
#pragma unroll
    for (int mt=0;mt<4;mt++)
#pragma unroll
        for (int nt=0;nt<4;nt++)
#pragma unroll
            for (int q=0;q<4;q++) acc[mt][nt][q] = 0.f;

    auto issue = [&](int kt, int s){
#pragma unroll
        for (int i0=0;i0<2;i0++){
            int i = tid + i0*256;
            int half = i >> 8, ii = i & 255, r = ii >> 1, c = ii & 1;
            const __half* src = half ? (g_Bh + (size_t)(j0+r)*DP + kt*16 + c*8)
                                     : (g_fh + (size_t)(b0+r)*DP + kt*16 + c*8);
            uint32_t dst = smb + (uint32_t)((s*3072 + half*1536 + r*12 + c*4)*4);
            cpa16(dst, src);
        }
        asm volatile("cp.async.commit_group;\n"::);
    };

    issue(0, 0);
    issue(1, 1);

#pragma unroll 1
    for (int kt = 0; kt < 11; kt++){
        int s = kt % 3;
        if (kt < 10) asm volatile("cp.async.wait_group 1;\n"::);
        else         asm volatile("cp.async.wait_group 0;\n"::);
        __syncthreads();

        const uint32_t baseA = smb + (uint32_t)(s*3072*4);
        const uint32_t baseB = baseA + 1536*4;

        uint32_t bh[4][2];
#pragma unroll
        for (int p=0;p<2;p++){
            uint32_t r[4];
            ldsm4(r, baseB + aoffB + (uint32_t)(p*16*12*4));
            bh[2*p][0]=r[0]; bh[2*p][1]=r[1]; bh[2*p+1][0]=r[2]; bh[2*p+1][1]=r[3];
        }
#pragma unroll
        for (int mt=0;mt<4;mt++){
            uint32_t ah[4];
            ldsm4(ah, baseA + aoffA + (uint32_t)(mt*16*12*4));
#pragma unroll
            for (int nt=0;nt<4;nt++){
                mmaf16(acc[mt][nt], ah[0],ah[1],ah[2],ah[3], bh[nt][0], bh[nt][1]);
            }
        }
        if (kt + 2 < 11) issue(kt+2, (kt+2) % 3);
    }

    const int g = lane >> 2;
    const int mcls = blockIdx.x >> 1;
    float2 ajv[4], cjv[4];
#pragma unroll
    for (int nt=0;nt<4;nt++){
        int j = j0 + joff + nt*8 + 2*t;
        ajv[nt] = *(const float2*)&g_Aj[j];
        cjv[nt] = *(const float2*)&g_Cj[j];
    }
#pragma unroll
    for (int mt=0;mt<4;mt++){
#pragma unroll
        for (int io=0; io<2; io++){
            int b = b0 + moff + mt*16 + g + io*8;
            float2 st = g_stats[b*MM + mcls];
            float rs = st.y, rm = st.y*st.x;
#pragma unroll
            for (int nt=0;nt<4;nt++){
                float c0 = acc[mt][nt][io*2], c1 = acc[mt][nt][io*2+1];
                float o0 = rs*c0 - rm*ajv[nt].x + cjv[nt].x;
                float o1 = rs*c1 - rm*ajv[nt].y + cjv[nt].y;
                __half2 h2 = __floats2half2_rn(o0, o1);
                *(__half2*)&g_priorsh[(size_t)b*JJ + j0 + joff + nt*8 + 2*t] = h2;
            }
        }
    }
}

// ---------------- per-b routing reduce (fp16 priors + f16 MMA votes, tanh sigmoid) ----------------
#define RSM_BYTES (528*24*2 + 528*34*2)
__global__ __launch_bounds__(256, 3) void k_reduce(const float* __restrict__ y,
                                                const float* __restrict__ thr,
                                                const float* __restrict__ clg,
                                                const float* __restrict__ clb,
                                                float* __restrict__ out){
    extern __shared__ __half hsm[];
    __half* sph = hsm;                 // [528][24] fp16 priors
    __half* svh = hsm + 528*24;        // [528][34] votes fp16
    __shared__ __half2 vb2[16*17];
    __shared__ float wg[528];
    __shared__ float sh[256];
    __shared__ float sy[4];
    __shared__ float snorm[16];
    __shared__ float sclg[16], sclb[16];
    __shared__ float smx[16], sinv[16];

    int b = blockIdx.x, tid = threadIdx.x;
    int warp = tid >> 5, lane = tid & 31;
    int g = lane >> 2, t = lane & 3;
    {
        const uint4* prow = (const uint4*)(g_priorsh + (size_t)b*JJ);
        for (int i=tid; i<1056; i+=256){
            uint4 v = prow[i];
            int mn = i >> 1, hf = i & 1;
            *(uint4*)&sph[mn*24 + hf*8] = v;
        }
    }
    if (tid < 4) sy[tid] = y[(size_t)b*4 + tid];
    if (tid < 16){ sclg[tid] = clg[tid]; sclb[tid] = clb[tid]; }

    uint32_t lbh[4][2], lbl[4][2];
    {
        const uint4* lf = (const uint4*)(g_lhsplit + lane*8);
        uint4 a0 = lf[0], a1 = lf[1];
        lbh[0][0]=a0.x; lbh[0][1]=a0.y; lbh[1][0]=a0.z; lbh[1][1]=a0.w;
        lbh[2][0]=a1.x; lbh[2][1]=a1.y; lbh[3][0]=a1.z; lbh[3][1]=a1.w;
        const uint4* lg = (const uint4*)(g_lhsplit + 256 + lane*8);
        uint4 b0v = lg[0], b1v = lg[1];
        lbl[0][0]=b0v.x; lbl[0][1]=b0v.y; lbl[1][0]=b0v.z; lbl[1][1]=b0v.w;
        lbl[2][0]=b1v.x; lbl[2][1]=b1v.y; lbl[3][0]=b1v.z; lbl[3][1]=b1v.w;
    }
    __syncthreads();

    const uint32_t spb = (uint32_t)__cvta_generic_to_shared(sph);
    for (int mt = warp; mt < 33; mt += 8){
        uint32_t ap[4];
        ldsm4(ap, spb + (uint32_t)(((mt*16 + (lane & 15))*24 + (lane >> 4)*8)*2));
        int r0 = mt*16 + g, r1 = r0 + 8;
#pragma unroll
        for (int nt=0;nt<4;nt++){
            float c[4] = {0.f,0.f,0.f,0.f};
            mmaf16(c, ap[0],ap[1],ap[2],ap[3], lbh[nt][0], lbh[nt][1]);
            mmaf16(c, ap[0],ap[1],ap[2],ap[3], lbl[nt][0], lbl[nt][1]);
            *(__half2*)&svh[r0*34 + nt*8 + 2*t] = __floats2half2_rn(sigt(c[0]), sigt(c[1]));
            *(__half2*)&svh[r1*34 + nt*8 + 2*t] = __floats2half2_rn(sigt(c[2]), sigt(c[3]));
        }
    }
    __syncthreads();
    {
        const __half2* sv2 = (const __half2*)svh;
        for (int i=tid; i<256; i+=256){
            int n = i >> 4, lp = i & 15;
            float ax = 0.f, ay = 0.f;
            for (int m=0;m<MM;m++){
                float2 f = __half22float2(sv2[(m*16+n)*17 + lp]);
                ax += f.x; ay += f.y;
            }
            vb2[n*17 + lp] = __floats2half2_rn(ax*(1.f/33.f), ay*(1.f/33.f));
        }
    }
    __syncthreads();
    {
        const __half2* sv2 = (const __half2*)svh;
        for (int i=tid; i<528; i+=256){
            int n = i & 15;
            float a = 0.f;
            for (int lp=0; lp<16; lp++){
                float2 v = __half22float2(sv2[i*17 + lp]);
                float2 m = __half22float2(vb2[n*17 + lp]);
                float dx = v.x - m.x, dy = v.y - m.y;
                a += dx*dx + dy*dy;
            }
            float tv = thr[i];
            float w = tv*tv - a*(1.f/32.f);
            wg[i] = (w > 0.f) ? w : 0.f;
        }
    }
    __syncthreads();
    if (tid < 16){
        float mx = -1e30f;
        for (int m=0;m<MM;m++) mx = fmaxf(mx, wg[m*16+tid]);
        smx[tid] = mx;
    }
    __syncthreads();
    for (int i=tid; i<528; i+=256) wg[i] = __expf(wg[i] - smx[i & 15]);
    __syncthreads();
    if (tid < 16){
        float s = 0.f;
        for (int m=0;m<MM;m++) s += wg[m*16+tid];
        sinv[tid] = 1.f/s;
    }
    __syncthreads();
    if (tid < 256){
        int n = tid >> 4, tt = tid & 15;
        float a = 0.f;
        for (int m=0;m<MM;m++) a += wg[m*16+n]*__half2float(sph[(m*16+n)*24 + tt]);
        sh[tid] = a * sinv[n];
    }
    __syncthreads();
    if (tid < 16){
        int n = tid;
        float s = 0.f, s2 = 0.f;
        for (int tt=0;tt<16;tt++){ float v = sh[n*16+tt]; s += v; s2 += v*v; }
        float mu = s*(1.f/16.f);
        float var = s2*(1.f/16.f) - mu*mu;
        float r = rsqrtf(fmaxf(var,0.f) + EPS_);
        float nn = 0.f;
        for (int tt=0;tt<16;tt++){
            float h = (sh[n*16+tt]-mu)*r*sclg[tt] + sclb[tt];
            sh[n*16+tt] = h;
            nn += h*h;
        }
        snorm[n] = sqrtf(nn);
    }
    __syncthreads();
    if (tid < 4)
        out[(size_t)b*4 + tid] = snorm[tid*4]+snorm[tid*4+1]+snorm[tid*4+2]+snorm[tid*4+3];
    if (tid < 64){
        int s = tid >> 4, tt = tid & 15;
        float a = 0.f;
#pragma unroll
        for (int c=0;c<4;c++) a += sy[c]*sh[(s*4+c)*16 + tt];
        g_hsel[(size_t)b*64 + tid] = a;
    }
}

// ---------------- decoder ----------------
__global__ __launch_bounds__(256) void k_dec1(){
    __shared__ float w[3*32*64];
    __shared__ float hs[32*65];
    int b0 = blockIdx.x*32, tid = threadIdx.x;
    for (int i=tid; i<6144; i+=256) w[i] = g_fc1m[i];
    for (int i=tid; i<2048; i+=256){
        int bl = i >> 6, d = i & 63;
        hs[bl*65 + d] = g_hsel[(size_t)(b0+bl)*64 + d];
    }
    __syncthreads();
    for (int idx=tid; idx<3072; idx+=256){
        int po = idx >> 5, bl = idx & 31;
        const float* wr = w + po*64;
        const float* hr = hs + bl*65;
        float a = 0.f;
#pragma unroll
        for (int d=0; d<64; d++) a += hr[d]*wr[d];
        g_hp1[(size_t)(b0+bl)*96 + po] = a;
    }
}

__global__ __launch_bounds__(256) void k_gbn1(const float* __restrict__ bg, const float* __restrict__ bb){
    int w = (blockIdx.x*256 + threadIdx.x) >> 5;
    int lane = threadIdx.x & 31;
    if (w >= 16*96) return;
    int g = w/96, k = w - g*96;
    const float* p = g_hp1 + (size_t)g*256*96 + k;
    float s = 0.f, s2 = 0.f;
#pragma unroll
    for (int i=0;i<8;i++){ float v = p[(size_t)(lane + i*32)*96]; s += v; s2 += v*v; }
    s = wsum(s); s2 = wsum(s2);
    if (lane == 0){
        float mu = s*(1.f/256.f);
        float var = s2*(1.f/256.f) - mu*mu;
        float r = rsqrtf(fmaxf(var,0.f) + EPS_);
        float a = bg[k]*r;
        g_gbn1[g*96 + k] = make_float2(a, bb[k] - mu*a);
    }
}

__global__ __launch_bounds__(256) void k_gbn2(const float* __restrict__ bg, const float* __restrict__ bb){
    int w = (blockIdx.x*256 + threadIdx.x) >> 5;
    int lane = threadIdx.x & 31;
    if (w >= 16*192) return;
    int g = w/192, k = w - g*192;
    const float* p = g_hp2 + (size_t)g*256*192 + k;
    float s = 0.f, s2 = 0.f;
#pragma unroll
    for (int i=0;i<8;i++){ float v = p[(size_t)(lane + i*32)*192]; s += v; s2 += v*v; }
    s = wsum(s); s2 = wsum(s2);
    if (lane == 0){
        float mu = s*(1.f/256.f);
        float var = s2*(1.f/256.f) - mu*mu;
        float r = rsqrtf(fmaxf(var,0.f) + EPS_);
        float a = bg[k]*r;
        g_gbn2[g*192 + k] = make_float2(a, bb[k] - mu*a);
    }
}

__global__ __launch_bounds__(256) void k_dec2(){
    extern __shared__ float dsm2[];
    float* w  = dsm2;           // 15360
    float* hs = dsm2 + 15360;   // 32*81
    int b0 = blockIdx.x*32, tid = threadIdx.x;
    for (int i=tid; i<15360; i+=256) w[i] = g_fc2m[i];
    for (int i=tid; i<2560; i+=256){
        int bl = i/80, d = i - bl*80;
        int b = b0 + bl;
        float v;
        if (d < 64){
            v = g_hsel[(size_t)b*64 + d];
        } else {
            int oo = d - 64, gg = b >> 8;
            v = 0.f;
#pragma unroll
            for (int p=0;p<3;p++){
                int k1 = p*32 + oo, k2 = k1 + 16;
                float2 t1 = g_gbn1[gg*96 + k1], t2 = g_gbn1[gg*96 + k2];
                float x1 = g_hp1[(size_t)b*96 + k1]*t1.x + t1.y;
                float x2 = g_hp1[(size_t)b*96 + k2]*t2.x + t2.y;
                float sg = 1.f/(1.f + __expf(-x1));
                v += fmaxf(sg*x2, 0.f);
            }
        }
        hs[bl*81 + d] = v;
    }
    __syncthreads();
    for (int idx=tid; idx<6144; idx+=256){
        int po = idx >> 5, bl = idx & 31;
        const float* wr = w + po*80;
        const float* hr = hs + bl*81;
        float a = 0.f;
#pragma unroll
        for (int d=0; d<80; d++) a += hr[d]*wr[d];
        g_hp2[(size_t)(b0+bl)*192 + po] = a;
    }
}

__global__ __launch_bounds__(256) void k_glu2rec(const float* __restrict__ dw,
                                                 const float* __restrict__ db,
                                                 float* __restrict__ out){
    __shared__ float so2[8*33];
    int b0 = blockIdx.x*8, tid = threadIdx.x;
    {
        int bl = tid >> 5, o = tid & 31;
        int b = b0 + bl, g = b >> 8;
        float a = 0.f;
#pragma unroll
        for (int p=0;p<3;p++){
            int k1 = p*64 + o, k2 = k1 + 32;
            float2 t1 = g_gbn2[g*192 + k1], t2 = g_gbn2[g*192 + k2];
            float x1 = g_hp2[(size_t)b*192 + k1]*t1.x + t1.y;
            float x2 = g_hp2[(size_t)b*192 + k2]*t2.x + t2.y;
            float sg = 1.f/(1.f + __expf(-x1));
            a += fmaxf(sg*x2, 0.f);
        }
        so2[bl*33 + o] = a;
    }
    __syncthreads();
    for (int i=tid; i<800; i+=256){
        int bl = i/100, o = i - bl*100;
        float a = db[o];
        const float* wr = dw + o*32;
        const float* sr = so2 + bl*33;
#pragma unroll
        for (int k=0;k<32;k++) a += sr[k]*wr[k];
        out[PREDSZ + (size_t)(b0+bl)*100 + o] = a;
    }
}

// ---------------- launcher ----------------
extern "C" void kernel_launch(void* const* d_in, const int* in_sizes, int n_in,
                              void* d_out, int out_size){
    const float* x      = (const float*)d_in[0];
    const float* y      = (const float*)d_in[1];
    const float* init_w = (const float*)d_in[2];
    const float* init_b = (const float*)d_in[3];
    const float* lng    = (const float*)d_in[4];
    const float* lnb    = (const float*)d_in[5];
    const float* prim   = (const float*)d_in[6];
    const float* routew = (const float*)d_in[7];
    const float* thr    = (const float*)d_in[8];
    const float* leaves = (const float*)d_in[9];
    const float* clg    = (const float*)d_in[10];
    const float* clb    = (const float*)d_in[11];
    const float* m1w    = (const float*)d_in[12];
    const float* fc1w   = (const float*)d_in[13];
    const float* bn1g   = (const float*)d_in[15];
    const float* bn1b   = (const float*)d_in[16];
    const float* m2w    = (const float*)d_in[17];
    const float* fc2w   = (const float*)d_in[18];
    const float* bn2g   = (const float*)d_in[20];
    const float* bn2b   = (const float*)d_in[21];
    const float* decw   = (const float*)d_in[22];
    const float* decb   = (const float*)d_in[23];
    float* out = (float*)d_out;

    cudaFuncSetAttribute(k_gemm,   cudaFuncAttributeMaxDynamicSharedMemorySize, 9216*4);
    cudaFuncSetAttribute(k_reduce, cudaFuncAttributeMaxDynamicSharedMemorySize, RSM_BYTES);
    cudaFuncSetAttribute(k_dec2,   cudaFuncAttributeMaxDynamicSharedMemorySize, (15360+32*81)*4);

    k_route<<<528, 256>>>(routew, prim, lng, lnb);
    k_const2<<<1, 256>>>(leaves, m1w, fc1w, m2w, fc2w);
    k_f<<<B_N, 256>>>(x, init_w, init_b, prim);
    {
        dim3 grid(JJ/128, B_N/128);
        k_gemm<<<grid, 256, 9216*4>>>();
    }
    k_reduce<<<B_N, 256, RSM_BYTES>>>(y, thr, clg, clb, out);
    k_dec1<<<B_N/32, 256>>>();
    k_gbn1<<<192, 256>>>(bn1g, bn1b);
    k_dec2<<<B_N/32, 256, (15360+32*81)*4>>>();
    k_gbn2<<<384, 256>>>(bn2g, bn2b);
    k_glu2rec<<<B_N/8, 256>>>(decw, decb, out);
}